// round 6
// baseline (speedup 1.0000x reference)
#include <cuda_runtime.h>
#include <math.h>

// Problem dims (fixed by the dataset)
#define BATCH  16
#define CDIM   256
#define HDIM   64
#define WDIM   64
#define HW     (HDIM * WDIM)        // 4096
#define NROWS  (BATCH * HW)         // 65536 pixels
#define KCODES 1024
#define ZSIZE  (BATCH * CDIM * HW)  // 16777216
#define NPART  (BATCH * (CDIM / 32) * (HW / 32))  // 16384 gather blocks
#define TAU    1e-3f                // margin threshold for precise re-scoring

// ---- scratch (static device globals; no runtime allocation) ----
__device__ float g_nrm[BATCH * CDIM * HDIM];          // per-(b,c,h) W-row norm
__device__ float g_zf[(size_t)NROWS * CDIM];          // normalized+transposed z [N,C]
__device__ float g_wn[KCODES * CDIM];                 // normalized codebook
__device__ float g_csq[KCODES];                       // ||wn_k||^2 (fp64-accurate, fp32-rounded)
__device__ int   g_idx[NROWS];                        // argmin indices
__device__ float g_part[NPART];                       // loss partial sums
__device__ int   g_nflag;                             // # near-tie pixels
__device__ int   g_flag[NROWS];                       // near-tie pixel list

// ---- packed f32x2 helpers (Blackwell 2xFP32 pipe; lane-wise IEEE fp32) ----
__device__ __forceinline__ unsigned long long pack2(float x, float y) {
    unsigned long long r;
    asm("mov.b64 %0, {%1, %2};" : "=l"(r) : "f"(x), "f"(y));
    return r;
}
__device__ __forceinline__ void unpack2(unsigned long long v, float& x, float& y) {
    asm("mov.b64 {%0, %1}, %2;" : "=f"(x), "=f"(y) : "l"(v));
}
__device__ __forceinline__ void fma2(unsigned long long& d,
                                     unsigned long long a, unsigned long long b) {
    asm("fma.rn.f32x2 %0, %1, %2, %0;" : "+l"(d) : "l"(a), "l"(b));
}

// ============================================================
// K1: per-(b,c,h) L2 norm over W (64 elems). fp64 accumulate -> fp32 sqrt.
// Also resets the near-tie counter (runs before k_argmin on same stream).
// ============================================================
__global__ void k_rownorm(const float* __restrict__ z) {
    if (blockIdx.x == 0 && threadIdx.x == 0) g_nflag = 0;
    int row  = blockIdx.x * 8 + (threadIdx.x >> 5);
    int lane = threadIdx.x & 31;
    const float* p = z + (size_t)row * WDIM;
    float v0 = p[lane], v1 = p[lane + 32];
    double s = (double)v0 * v0 + (double)v1 * v1;
    #pragma unroll
    for (int o = 16; o; o >>= 1) s += __shfl_xor_sync(0xffffffffu, s, o);
    if (lane == 0) g_nrm[row] = fmaxf(__fsqrt_rn((float)s), 1e-12f);
}

// ============================================================
// K1b: normalize codebook rows (C=256) with fp64 accumulation; csq fp64->fp32.
// Warp per codeword, 8 warps/block.
// ============================================================
__global__ void k_codebook(const float* __restrict__ emb) {
    int k    = blockIdx.x * 8 + (threadIdx.x >> 5);
    int lane = threadIdx.x & 31;
    const float* e = emb + (size_t)k * CDIM;
    float v[8];
    double s = 0.0;
    #pragma unroll
    for (int i = 0; i < 8; i++) { v[i] = e[lane + i * 32]; s += (double)v[i] * v[i]; }
    #pragma unroll
    for (int o = 16; o; o >>= 1) s += __shfl_xor_sync(0xffffffffu, s, o);
    float n = fmaxf(__fsqrt_rn((float)s), 1e-12f);
    float* w = g_wn + (size_t)k * CDIM;
    double s2 = 0.0;
    #pragma unroll
    for (int i = 0; i < 8; i++) {
        float t = __fdiv_rn(v[i], n);
        w[lane + i * 32] = t;
        s2 += (double)t * t;
    }
    #pragma unroll
    for (int o = 16; o; o >>= 1) s2 += __shfl_xor_sync(0xffffffffu, s2, o);
    if (lane == 0) g_csq[k] = (float)s2;
}

// ============================================================
// K2: fused normalize (divide by W-row norm) + transpose [B,C,HW] -> [B*HW, C].
// ============================================================
__global__ void k_transpose(const float* __restrict__ z) {
    __shared__ float tile[32][33];
    int b = blockIdx.z, c0 = blockIdx.y * 32, hw0 = blockIdx.x * 32;
    int tx = threadIdx.x, ty = threadIdx.y;
    int h = hw0 >> 6;
    #pragma unroll
    for (int i = 0; i < 4; i++) {
        int c = c0 + ty + i * 8;
        float v = z[((size_t)(b * CDIM + c)) * HW + hw0 + tx];
        v = __fdiv_rn(v, g_nrm[(b * CDIM + c) * HDIM + h]);
        tile[ty + i * 8][tx] = v;
    }
    __syncthreads();
    #pragma unroll
    for (int i = 0; i < 4; i++) {
        int hwl = ty + i * 8;
        g_zf[((size_t)(b * HW + hw0 + hwl)) * CDIM + c0 + tx] = tile[tx][hwl];
    }
}

// ============================================================
// K3: fused GEMM + argmin with SECOND-BEST (margin) tracking.
//   score(n,k) = csq_k - 2*dot(zf_n, wn_k)   (||zf_n||^2 const/row, dropped)
// Inner product uses packed fma.rn.f32x2 (lane-wise identical to scalar FFMA).
// Pixels with (second - best) < TAU get flagged for precise re-scoring.
// ============================================================
__global__ __launch_bounds__(256) void k_argmin(float* __restrict__ outIdxF) {
    __shared__ union SmU {
        struct { float A[32][132]; float B[32][132]; } g;   // GEMM tiles
        struct { float rs[128][16]; float rs2[128][16]; int rk[128][16]; } r;
    } sm;

    int tid = threadIdx.x;
    int tx = tid & 15, ty = tid >> 4;
    size_t rowBase = (size_t)blockIdx.x * 128;

    float bests[8], bests2[8];
    int   bestk[8];
    #pragma unroll
    for (int i = 0; i < 8; i++) { bests[i] = 3.0e38f; bests2[i] = 3.0e38f; bestk[i] = 0; }

    for (int kb = 0; kb < KCODES; kb += 128) {
        // acc2[i][p] holds (acc[i][2p], acc[i][2p+1]) as packed f32x2
        unsigned long long acc2[8][4];
        unsigned long long zz = pack2(0.f, 0.f);
        #pragma unroll
        for (int i = 0; i < 8; i++)
            #pragma unroll
            for (int p = 0; p < 4; p++) acc2[i][p] = zz;

        for (int cb = 0; cb < CDIM; cb += 32) {
            #pragma unroll
            for (int i = 0; i < 4; i++) {
                int s = tid + i * 256;
                int r = s >> 3, c4 = (s & 7) * 4;
                float4 va = *(const float4*)(g_zf + (rowBase + r) * CDIM + cb + c4);
                sm.g.A[c4 + 0][r] = va.x; sm.g.A[c4 + 1][r] = va.y;
                sm.g.A[c4 + 2][r] = va.z; sm.g.A[c4 + 3][r] = va.w;
                float4 vb = *(const float4*)(g_wn + (size_t)(kb + r) * CDIM + cb + c4);
                sm.g.B[c4 + 0][r] = vb.x; sm.g.B[c4 + 1][r] = vb.y;
                sm.g.B[c4 + 2][r] = vb.z; sm.g.B[c4 + 3][r] = vb.w;
            }
            __syncthreads();
            #pragma unroll
            for (int kk = 0; kk < 32; kk++) {
                float a[8], bb[8];
                *(float4*)(a)      = *(const float4*)&sm.g.A[kk][ty * 8];
                *(float4*)(a + 4)  = *(const float4*)&sm.g.A[kk][ty * 8 + 4];
                *(float4*)(bb)     = *(const float4*)&sm.g.B[kk][tx * 8];
                *(float4*)(bb + 4) = *(const float4*)&sm.g.B[kk][tx * 8 + 4];
                unsigned long long bp[4];
                #pragma unroll
                for (int p = 0; p < 4; p++) bp[p] = pack2(bb[2 * p], bb[2 * p + 1]);
                #pragma unroll
                for (int i = 0; i < 8; i++) {
                    unsigned long long ap = pack2(a[i], a[i]);
                    #pragma unroll
                    for (int p = 0; p < 4; p++) fma2(acc2[i][p], ap, bp[p]);
                }
            }
            __syncthreads();
        }
        // fold this k-chunk into running (best, second) — kcol ascending per thread
        #pragma unroll
        for (int i = 0; i < 8; i++) {
            float accf[8];
            #pragma unroll
            for (int p = 0; p < 4; p++) unpack2(acc2[i][p], accf[2 * p], accf[2 * p + 1]);
            #pragma unroll
            for (int j = 0; j < 8; j++) {
                int kcol = kb + tx * 8 + j;
                float sc = fmaf(-2.0f, accf[j], g_csq[kcol]);
                if (sc < bests[i]) {
                    bests2[i] = bests[i];
                    bests[i] = sc; bestk[i] = kcol;
                } else if (sc < bests2[i]) {
                    bests2[i] = sc;
                }
            }
        }
    }

    __syncthreads();   // GEMM tiles dead; reuse smem for reductions
    #pragma unroll
    for (int i = 0; i < 8; i++) {
        sm.r.rs [ty * 8 + i][tx] = bests[i];
        sm.r.rs2[ty * 8 + i][tx] = bests2[i];
        sm.r.rk [ty * 8 + i][tx] = bestk[i];
    }
    __syncthreads();
    if (tid < 128) {
        float w1 = 3.0e38f, w2 = 3.0e38f;
        int   k1 = 0x7fffffff;
        #pragma unroll
        for (int t = 0; t < 16; t++) {
            float s1 = sm.r.rs[tid][t];
            int   kk = sm.r.rk[tid][t];
            if (s1 < w1 || (s1 == w1 && kk < k1)) {
                w2 = fminf(w2, w1);
                w1 = s1; k1 = kk;
            } else {
                w2 = fminf(w2, s1);
            }
            w2 = fminf(w2, sm.r.rs2[tid][t]);
        }
        size_t n = rowBase + tid;
        g_idx[n]   = k1;
        outIdxF[n] = (float)k1;
        if (w2 - w1 < TAU) {
            int pos = atomicAdd(&g_nflag, 1);
            g_flag[pos] = (int)n;
        }
    }
}

// ============================================================
// K3b: precise re-scoring of near-tie pixels.
// Dot2 (compensated fp32) dot products == correctly rounded; then the
// reference's exact fp32 formula: d = fl(fl(rowsq + csq) - fl(2*dot)),
// argmin with first-index tie-break.
// ============================================================
__device__ __forceinline__ float dot2_256(const float* __restrict__ a,
                                          const float* __restrict__ b) {
    float s = 0.f, comp = 0.f;
    #pragma unroll 8
    for (int c = 0; c < CDIM; c++) {
        float p  = __fmul_rn(a[c], b[c]);
        float e  = __fmaf_rn(a[c], b[c], -p);       // exact product error
        float t  = __fadd_rn(s, p);                 // TwoSum
        float bv = __fsub_rn(t, s);
        float e2 = __fadd_rn(__fsub_rn(s, __fsub_rn(t, bv)), __fsub_rn(p, bv));
        comp = __fadd_rn(comp, __fadd_rn(e, e2));
        s = t;
    }
    return __fadd_rn(s, comp);
}

__global__ __launch_bounds__(256) void k_precise(float* __restrict__ outIdxF) {
    __shared__ float szf[CDIM];
    __shared__ float srq;
    __shared__ float rs[256];
    __shared__ int   rk[256];
    int nf = g_nflag;
    for (int it = blockIdx.x; it < nf; it += gridDim.x) {
        int n = g_flag[it];
        szf[threadIdx.x] = g_zf[(size_t)n * CDIM + threadIdx.x];
        __syncthreads();
        if (threadIdx.x == 0) srq = dot2_256(szf, szf);
        __syncthreads();
        float rq = srq;
        float bs = 3.0e38f;
        int   bk = 0x7fffffff;
        #pragma unroll
        for (int j = 0; j < 4; j++) {
            int k = threadIdx.x + j * 256;
            float dot = dot2_256(szf, g_wn + (size_t)k * CDIM);
            float d = __fsub_rn(__fadd_rn(rq, g_csq[k]), __fmul_rn(2.0f, dot));
            if (d < bs || (d == bs && k < bk)) { bs = d; bk = k; }
        }
        rs[threadIdx.x] = bs; rk[threadIdx.x] = bk;
        __syncthreads();
        if (threadIdx.x == 0) {
            float b = rs[0]; int kk = rk[0];
            #pragma unroll 8
            for (int t = 1; t < 256; t++) {
                if (rs[t] < b || (rs[t] == b && rk[t] < kk)) { b = rs[t]; kk = rk[t]; }
            }
            g_idx[n]   = kk;
            outIdxF[n] = (float)kk;
        }
        __syncthreads();
    }
}

// ============================================================
// K4: gather codewords, straight-through zp + (e - zp), transpose back,
// accumulate loss partials (deterministic, no float atomics).
// ============================================================
__global__ void k_gather(float* __restrict__ out, const float* __restrict__ emb) {
    __shared__ float tile[32][33];
    __shared__ float red[8];
    int b = blockIdx.z, c0 = blockIdx.y * 32, hw0 = blockIdx.x * 32;
    int tx = threadIdx.x, ty = threadIdx.y;
    float lsum = 0.f;
    #pragma unroll
    for (int i = 0; i < 4; i++) {
        int hwl = ty + i * 8;
        size_t n = (size_t)b * HW + hw0 + hwl;
        float zp = g_zf[n * CDIM + c0 + tx];
        int   k  = g_idx[n];
        float e  = emb[(size_t)k * CDIM + c0 + tx];
        float d  = __fsub_rn(e, zp);
        tile[hwl][tx] = __fadd_rn(zp, d);  // straight-through, reference fp order
        lsum = __fmaf_rn(d, d, lsum);
    }
    __syncthreads();
    #pragma unroll
    for (int i = 0; i < 4; i++) {
        int cl = ty + i * 8;
        out[((size_t)(b * CDIM + c0 + cl)) * HW + hw0 + tx] = tile[tx][cl];
    }
    #pragma unroll
    for (int o = 16; o; o >>= 1) lsum += __shfl_xor_sync(0xffffffffu, lsum, o);
    int tid = ty * 32 + tx;
    if ((tid & 31) == 0) red[tid >> 5] = lsum;
    __syncthreads();
    if (tid == 0) {
        float s = 0.f;
        #pragma unroll
        for (int w = 0; w < 8; w++) s += red[w];
        g_part[((size_t)blockIdx.z * gridDim.y + blockIdx.y) * gridDim.x + blockIdx.x] = s;
    }
}

// ============================================================
// K5: final loss. loss = (BETA + 1) * mean(diff^2) = 1.25 * sum / ZSIZE
// ============================================================
__global__ void k_loss(float* __restrict__ out) {
    __shared__ float red[8];
    int tid = threadIdx.x;
    float s = 0.f;
    for (int i = tid; i < NPART; i += 256) s += g_part[i];
    #pragma unroll
    for (int o = 16; o; o >>= 1) s += __shfl_xor_sync(0xffffffffu, s, o);
    if ((tid & 31) == 0) red[tid >> 5] = s;
    __syncthreads();
    if (tid == 0) {
        float t = 0.f;
        #pragma unroll
        for (int w = 0; w < 8; w++) t += red[w];
        out[(size_t)ZSIZE + NROWS] = 1.25f * t / (float)ZSIZE;
    }
}

// ============================================================
// launch: out layout = [ z_q (16777216 f32) | idx-as-f32 (65536) | loss (1) ]
// ============================================================
extern "C" void kernel_launch(void* const* d_in, const int* in_sizes, int n_in,
                              void* d_out, int out_size) {
    const float* z   = (const float*)d_in[0];
    const float* emb = (const float*)d_in[1];
    float* out = (float*)d_out;

    k_rownorm <<<BATCH * CDIM * HDIM / 8, 256>>>(z);
    k_codebook<<<KCODES / 8, 256>>>(emb);
    k_transpose<<<dim3(HW / 32, CDIM / 32, BATCH), dim3(32, 8)>>>(z);
    k_argmin  <<<NROWS / 128, 256>>>(out + ZSIZE);
    k_precise <<<128, 256>>>(out + ZSIZE);
    k_gather  <<<dim3(HW / 32, CDIM / 32, BATCH), dim3(32, 8)>>>(out, emb);
    k_loss    <<<1, 256>>>(out);
}

// round 7
// speedup vs baseline: 1.8013x; 1.8013x over previous
#include <cuda_runtime.h>
#include <math.h>

// Problem dims (fixed by the dataset)
#define BATCH  16
#define CDIM   256
#define HDIM   64
#define WDIM   64
#define HW     (HDIM * WDIM)        // 4096
#define NROWS  (BATCH * HW)         // 65536 pixels
#define KCODES 1024
#define ZSIZE  (BATCH * CDIM * HW)  // 16777216
#define NPART  (BATCH * (CDIM / 32) * (HW / 32))  // 16384 gather blocks
#define TAU    1e-4f                // margin threshold for precise re-scoring

// ---- scratch (static device globals; no runtime allocation) ----
__device__ float g_nrm[BATCH * CDIM * HDIM];          // per-(b,c,h) W-row norm
__device__ float g_zf[(size_t)NROWS * CDIM];          // normalized+transposed z [N,C]
__device__ float g_wn[KCODES * CDIM];                 // normalized codebook
__device__ float g_csq[KCODES];                       // ||wn_k||^2 (fp64-accurate, fp32-rounded)
__device__ int   g_idx[NROWS];                        // argmin indices
__device__ float g_part[NPART];                       // loss partial sums
__device__ int   g_nflag;                             // # near-tie pixels
__device__ int   g_flag[NROWS];                       // near-tie pixel list

// ---- packed f32x2 helpers (Blackwell 2xFP32 pipe; lane-wise IEEE fp32) ----
__device__ __forceinline__ unsigned long long pack2(float x, float y) {
    unsigned long long r;
    asm("mov.b64 %0, {%1, %2};" : "=l"(r) : "f"(x), "f"(y));
    return r;
}
__device__ __forceinline__ void unpack2(unsigned long long v, float& x, float& y) {
    asm("mov.b64 {%0, %1}, %2;" : "=f"(x), "=f"(y) : "l"(v));
}
__device__ __forceinline__ void fma2(unsigned long long& d,
                                     unsigned long long a, unsigned long long b) {
    asm("fma.rn.f32x2 %0, %1, %2, %0;" : "+l"(d) : "l"(a), "l"(b));
}

// ============================================================
// K1: per-(b,c,h) L2 norm over W (64 elems). fp64 accumulate -> fp32 sqrt.
// Also resets the near-tie counter (runs before k_argmin on same stream).
// ============================================================
__global__ void k_rownorm(const float* __restrict__ z) {
    if (blockIdx.x == 0 && threadIdx.x == 0) g_nflag = 0;
    int row  = blockIdx.x * 8 + (threadIdx.x >> 5);
    int lane = threadIdx.x & 31;
    const float* p = z + (size_t)row * WDIM;
    float v0 = p[lane], v1 = p[lane + 32];
    double s = (double)v0 * v0 + (double)v1 * v1;
    #pragma unroll
    for (int o = 16; o; o >>= 1) s += __shfl_xor_sync(0xffffffffu, s, o);
    if (lane == 0) g_nrm[row] = fmaxf(__fsqrt_rn((float)s), 1e-12f);
}

// ============================================================
// K1b: normalize codebook rows (C=256) with fp64 accumulation; csq fp64->fp32.
// ============================================================
__global__ void k_codebook(const float* __restrict__ emb) {
    int k    = blockIdx.x * 8 + (threadIdx.x >> 5);
    int lane = threadIdx.x & 31;
    const float* e = emb + (size_t)k * CDIM;
    float v[8];
    double s = 0.0;
    #pragma unroll
    for (int i = 0; i < 8; i++) { v[i] = e[lane + i * 32]; s += (double)v[i] * v[i]; }
    #pragma unroll
    for (int o = 16; o; o >>= 1) s += __shfl_xor_sync(0xffffffffu, s, o);
    float n = fmaxf(__fsqrt_rn((float)s), 1e-12f);
    float* w = g_wn + (size_t)k * CDIM;
    double s2 = 0.0;
    #pragma unroll
    for (int i = 0; i < 8; i++) {
        float t = __fdiv_rn(v[i], n);
        w[lane + i * 32] = t;
        s2 += (double)t * t;
    }
    #pragma unroll
    for (int o = 16; o; o >>= 1) s2 += __shfl_xor_sync(0xffffffffu, s2, o);
    if (lane == 0) g_csq[k] = (float)s2;
}

// ============================================================
// K2: fused normalize (divide by W-row norm) + transpose [B,C,HW] -> [B*HW, C].
// ============================================================
__global__ void k_transpose(const float* __restrict__ z) {
    __shared__ float tile[32][33];
    int b = blockIdx.z, c0 = blockIdx.y * 32, hw0 = blockIdx.x * 32;
    int tx = threadIdx.x, ty = threadIdx.y;
    int h = hw0 >> 6;
    #pragma unroll
    for (int i = 0; i < 4; i++) {
        int c = c0 + ty + i * 8;
        float v = z[((size_t)(b * CDIM + c)) * HW + hw0 + tx];
        v = __fdiv_rn(v, g_nrm[(b * CDIM + c) * HDIM + h]);
        tile[ty + i * 8][tx] = v;
    }
    __syncthreads();
    #pragma unroll
    for (int i = 0; i < 4; i++) {
        int hwl = ty + i * 8;
        g_zf[((size_t)(b * HW + hw0 + hwl)) * CDIM + c0 + tx] = tile[tx][hwl];
    }
}

// ============================================================
// K3: fused GEMM + argmin with SECOND-BEST (margin) tracking.
//   score(n,k) = csq_k - 2*dot(zf_n, wn_k)   (||zf_n||^2 const/row, dropped)
// Conflict-free B fetch: thread's 8 codes = {4tx..4tx+3} u {64+4tx..64+4tx+3}
// so each half-warp's LDS.128 covers 256B contiguous (degree-1).
// kcol ascending per thread preserves first-index tie semantics.
// ============================================================
__global__ __launch_bounds__(256) void k_argmin(float* __restrict__ outIdxF) {
    __shared__ union SmU {
        struct { float A[32][132]; float B[32][132]; } g;   // GEMM tiles
        struct { float rs[128][16]; float rs2[128][16]; int rk[128][16]; } r;
    } sm;

    int tid = threadIdx.x;
    int tx = tid & 15, ty = tid >> 4;
    size_t rowBase = (size_t)blockIdx.x * 128;

    float bests[8], bests2[8];
    int   bestk[8];
    #pragma unroll
    for (int i = 0; i < 8; i++) { bests[i] = 3.0e38f; bests2[i] = 3.0e38f; bestk[i] = 0; }

    for (int kb = 0; kb < KCODES; kb += 128) {
        // acc2[i][p]: p=0,1 -> codes 4tx+2p,4tx+2p+1 ; p=2,3 -> 64+4tx+2(p-2),+1
        unsigned long long acc2[8][4];
        unsigned long long zz = pack2(0.f, 0.f);
        #pragma unroll
        for (int i = 0; i < 8; i++)
            #pragma unroll
            for (int p = 0; p < 4; p++) acc2[i][p] = zz;

        for (int cb = 0; cb < CDIM; cb += 32) {
            #pragma unroll
            for (int i = 0; i < 4; i++) {
                int s = tid + i * 256;
                int r = s >> 3, c4 = (s & 7) * 4;
                float4 va = *(const float4*)(g_zf + (rowBase + r) * CDIM + cb + c4);
                sm.g.A[c4 + 0][r] = va.x; sm.g.A[c4 + 1][r] = va.y;
                sm.g.A[c4 + 2][r] = va.z; sm.g.A[c4 + 3][r] = va.w;
                float4 vb = *(const float4*)(g_wn + (size_t)(kb + r) * CDIM + cb + c4);
                sm.g.B[c4 + 0][r] = vb.x; sm.g.B[c4 + 1][r] = vb.y;
                sm.g.B[c4 + 2][r] = vb.z; sm.g.B[c4 + 3][r] = vb.w;
            }
            __syncthreads();
            #pragma unroll
            for (int kk = 0; kk < 32; kk++) {
                float a[8], bb[8];
                *(float4*)(a)      = *(const float4*)&sm.g.A[kk][ty * 8];
                *(float4*)(a + 4)  = *(const float4*)&sm.g.A[kk][ty * 8 + 4];
                // conflict-free: 16 lanes x float4 = contiguous 256B per half-tile
                *(float4*)(bb)     = *(const float4*)&sm.g.B[kk][tx * 4];
                *(float4*)(bb + 4) = *(const float4*)&sm.g.B[kk][64 + tx * 4];
                unsigned long long bp[4];
                #pragma unroll
                for (int p = 0; p < 4; p++) bp[p] = pack2(bb[2 * p], bb[2 * p + 1]);
                #pragma unroll
                for (int i = 0; i < 8; i++) {
                    unsigned long long ap = pack2(a[i], a[i]);
                    #pragma unroll
                    for (int p = 0; p < 4; p++) fma2(acc2[i][p], ap, bp[p]);
                }
            }
            __syncthreads();
        }
        // fold into running (best, second); per-thread kcol ascending in j
        #pragma unroll
        for (int i = 0; i < 8; i++) {
            float accf[8];
            #pragma unroll
            for (int p = 0; p < 4; p++) unpack2(acc2[i][p], accf[2 * p], accf[2 * p + 1]);
            #pragma unroll
            for (int j = 0; j < 8; j++) {
                int kcol = kb + ((j < 4) ? (tx * 4 + j) : (64 + tx * 4 + j - 4));
                float sc = fmaf(-2.0f, accf[j], g_csq[kcol]);
                if (sc < bests[i]) {
                    bests2[i] = bests[i];
                    bests[i] = sc; bestk[i] = kcol;
                } else if (sc < bests2[i]) {
                    bests2[i] = sc;
                }
            }
        }
    }

    __syncthreads();   // GEMM tiles dead; reuse smem for reductions
    #pragma unroll
    for (int i = 0; i < 8; i++) {
        sm.r.rs [ty * 8 + i][tx] = bests[i];
        sm.r.rs2[ty * 8 + i][tx] = bests2[i];
        sm.r.rk [ty * 8 + i][tx] = bestk[i];
    }
    __syncthreads();
    if (tid < 128) {
        float w1 = 3.0e38f, w2 = 3.0e38f;
        int   k1 = 0x7fffffff;
        #pragma unroll
        for (int t = 0; t < 16; t++) {
            float s1 = sm.r.rs[tid][t];
            int   kk = sm.r.rk[tid][t];
            if (s1 < w1 || (s1 == w1 && kk < k1)) {
                w2 = fminf(w2, w1);
                w1 = s1; k1 = kk;
            } else {
                w2 = fminf(w2, s1);
            }
            w2 = fminf(w2, sm.r.rs2[tid][t]);
        }
        size_t n = rowBase + tid;
        g_idx[n]   = k1;
        outIdxF[n] = (float)k1;
        if (w2 - w1 < TAU) {
            int pos = atomicAdd(&g_nflag, 1);
            g_flag[pos] = (int)n;
        }
    }
}

// ============================================================
// K3b: precise re-scoring of near-tie pixels.
// Dot2 (compensated fp32) dot products == correctly rounded; then the
// reference's exact fp32 formula: d = fl(fl(rowsq + csq) - fl(2*dot)),
// argmin with first-index tie-break.
// ============================================================
__device__ __forceinline__ float dot2_256(const float* __restrict__ a,
                                          const float* __restrict__ b) {
    float s = 0.f, comp = 0.f;
    #pragma unroll 8
    for (int c = 0; c < CDIM; c++) {
        float p  = __fmul_rn(a[c], b[c]);
        float e  = __fmaf_rn(a[c], b[c], -p);       // exact product error
        float t  = __fadd_rn(s, p);                 // TwoSum
        float bv = __fsub_rn(t, s);
        float e2 = __fadd_rn(__fsub_rn(s, __fsub_rn(t, bv)), __fsub_rn(p, bv));
        comp = __fadd_rn(comp, __fadd_rn(e, e2));
        s = t;
    }
    return __fadd_rn(s, comp);
}

__global__ __launch_bounds__(256) void k_precise(float* __restrict__ outIdxF) {
    __shared__ float szf[CDIM];
    __shared__ float srq;
    __shared__ float rs[256];
    __shared__ int   rk[256];
    int nf = g_nflag;
    for (int it = blockIdx.x; it < nf; it += gridDim.x) {
        int n = g_flag[it];
        szf[threadIdx.x] = g_zf[(size_t)n * CDIM + threadIdx.x];
        __syncthreads();
        if (threadIdx.x == 0) srq = dot2_256(szf, szf);
        __syncthreads();
        float rq = srq;
        float bs = 3.0e38f;
        int   bk = 0x7fffffff;
        #pragma unroll
        for (int j = 0; j < 4; j++) {
            int k = threadIdx.x + j * 256;
            float dot = dot2_256(szf, g_wn + (size_t)k * CDIM);
            float d = __fsub_rn(__fadd_rn(rq, g_csq[k]), __fmul_rn(2.0f, dot));
            if (d < bs || (d == bs && k < bk)) { bs = d; bk = k; }
        }
        rs[threadIdx.x] = bs; rk[threadIdx.x] = bk;
        __syncthreads();
        if (threadIdx.x == 0) {
            float b = rs[0]; int kk = rk[0];
            #pragma unroll 8
            for (int t = 1; t < 256; t++) {
                if (rs[t] < b || (rs[t] == b && rk[t] < kk)) { b = rs[t]; kk = rk[t]; }
            }
            g_idx[n]   = kk;
            outIdxF[n] = (float)kk;
        }
        __syncthreads();
    }
}

// ============================================================
// K4: gather codewords, straight-through zp + (e - zp), transpose back,
// accumulate loss partials (deterministic, no float atomics).
// ============================================================
__global__ void k_gather(float* __restrict__ out, const float* __restrict__ emb) {
    __shared__ float tile[32][33];
    __shared__ float red[8];
    int b = blockIdx.z, c0 = blockIdx.y * 32, hw0 = blockIdx.x * 32;
    int tx = threadIdx.x, ty = threadIdx.y;
    float lsum = 0.f;
    #pragma unroll
    for (int i = 0; i < 4; i++) {
        int hwl = ty + i * 8;
        size_t n = (size_t)b * HW + hw0 + hwl;
        float zp = g_zf[n * CDIM + c0 + tx];
        int   k  = g_idx[n];
        float e  = emb[(size_t)k * CDIM + c0 + tx];
        float d  = __fsub_rn(e, zp);
        tile[hwl][tx] = __fadd_rn(zp, d);  // straight-through, reference fp order
        lsum = __fmaf_rn(d, d, lsum);
    }
    __syncthreads();
    #pragma unroll
    for (int i = 0; i < 4; i++) {
        int cl = ty + i * 8;
        out[((size_t)(b * CDIM + c0 + cl)) * HW + hw0 + tx] = tile[tx][cl];
    }
    #pragma unroll
    for (int o = 16; o; o >>= 1) lsum += __shfl_xor_sync(0xffffffffu, lsum, o);
    int tid = ty * 32 + tx;
    if ((tid & 31) == 0) red[tid >> 5] = lsum;
    __syncthreads();
    if (tid == 0) {
        float s = 0.f;
        #pragma unroll
        for (int w = 0; w < 8; w++) s += red[w];
        g_part[((size_t)blockIdx.z * gridDim.y + blockIdx.y) * gridDim.x + blockIdx.x] = s;
    }
}

// ============================================================
// K5: final loss. loss = (BETA + 1) * mean(diff^2) = 1.25 * sum / ZSIZE
// ============================================================
__global__ void k_loss(float* __restrict__ out) {
    __shared__ float red[8];
    int tid = threadIdx.x;
    float s = 0.f;
    for (int i = tid; i < NPART; i += 256) s += g_part[i];
    #pragma unroll
    for (int o = 16; o; o >>= 1) s += __shfl_xor_sync(0xffffffffu, s, o);
    if ((tid & 31) == 0) red[tid >> 5] = s;
    __syncthreads();
    if (tid == 0) {
        float t = 0.f;
        #pragma unroll
        for (int w = 0; w < 8; w++) t += red[w];
        out[(size_t)ZSIZE + NROWS] = 1.25f * t / (float)ZSIZE;
    }
}

// ============================================================
// launch: out layout = [ z_q (16777216 f32) | idx-as-f32 (65536) | loss (1) ]
// ============================================================
extern "C" void kernel_launch(void* const* d_in, const int* in_sizes, int n_in,
                              void* d_out, int out_size) {
    const float* z   = (const float*)d_in[0];
    const float* emb = (const float*)d_in[1];
    float* out = (float*)d_out;

    k_rownorm <<<BATCH * CDIM * HDIM / 8, 256>>>(z);
    k_codebook<<<KCODES / 8, 256>>>(emb);
    k_transpose<<<dim3(HW / 32, CDIM / 32, BATCH), dim3(32, 8)>>>(z);
    k_argmin  <<<NROWS / 128, 256>>>(out + ZSIZE);
    k_precise <<<256, 256>>>(out + ZSIZE);
    k_gather  <<<dim3(HW / 32, CDIM / 32, BATCH), dim3(32, 8)>>>(out, emb);
    k_loss    <<<1, 256>>>(out);
}

// round 15
// speedup vs baseline: 2.6603x; 1.4769x over previous
#include <cuda_runtime.h>
#include <cuda_bf16.h>
#include <stdint.h>
#include <cstdint>
#include <math.h>

// Problem dims (fixed by the dataset)
#define BATCH  16
#define CDIM   256
#define HDIM   64
#define WDIM   64
#define HW     (HDIM * WDIM)        // 4096
#define NROWS  (BATCH * HW)         // 65536 pixels
#define KCODES 1024
#define ZSIZE  (BATCH * CDIM * HW)  // 16777216
#define NPART  (BATCH * (CDIM / 32) * (HW / 32))  // 16384 gather blocks
#define TAU    1e-4f                // margin threshold for precise re-scoring
#define APAD   264                  // padded row (bf16 elems): 528B = +4 banks/row

// ---- scratch (static device globals; no runtime allocation) ----
__device__ float g_nrm[BATCH * CDIM * HDIM];          // per-(b,c,h) W-row norm
__device__ float g_zf[(size_t)NROWS * CDIM];          // normalized+transposed z [N,C] fp32
__device__ __nv_bfloat16 g_zh[(size_t)NROWS * CDIM];  // bf16 hi of zf
__device__ __nv_bfloat16 g_zl[(size_t)NROWS * CDIM];  // bf16 lo of zf
__device__ float g_wn[KCODES * CDIM];                 // normalized codebook fp32
__device__ __nv_bfloat16 g_wh[KCODES * CDIM];         // bf16 hi of wn
__device__ __nv_bfloat16 g_wl[KCODES * CDIM];         // bf16 lo of wn
__device__ float g_csq[KCODES];                       // ||wn_k||^2 (fp64-accurate)
__device__ int   g_idx[NROWS];                        // argmin indices
__device__ float g_part[NPART];                       // loss partial sums
__device__ int   g_nflag;                             // # near-tie pixels
__device__ int   g_flag[NROWS];                       // near-tie pixel list

// ---- tensor-core helpers ----
__device__ __forceinline__ uint32_t smem_u32(const void* p) {
    return (uint32_t)__cvta_generic_to_shared(p);
}
__device__ __forceinline__ void ldsm4(uint32_t* r, uint32_t addr) {
    asm volatile("ldmatrix.sync.aligned.m8n8.x4.shared.b16 {%0,%1,%2,%3}, [%4];"
        : "=r"(r[0]), "=r"(r[1]), "=r"(r[2]), "=r"(r[3]) : "r"(addr));
}
__device__ __forceinline__ void mma_bf16(float* c, const uint32_t* a, const uint32_t* b) {
    asm volatile("mma.sync.aligned.m16n8k16.row.col.f32.bf16.bf16.f32 "
        "{%0,%1,%2,%3}, {%4,%5,%6,%7}, {%8,%9}, {%0,%1,%2,%3};"
        : "+f"(c[0]), "+f"(c[1]), "+f"(c[2]), "+f"(c[3])
        : "r"(a[0]), "r"(a[1]), "r"(a[2]), "r"(a[3]), "r"(b[0]), "r"(b[1]));
}

// ============================================================
// K1: per-(b,c,h) L2 norm over W (64). fp64 accumulate -> fp32 sqrt.
// ============================================================
__global__ void k_rownorm(const float* __restrict__ z) {
    if (blockIdx.x == 0 && threadIdx.x == 0) g_nflag = 0;
    int row  = blockIdx.x * 8 + (threadIdx.x >> 5);
    int lane = threadIdx.x & 31;
    const float* p = z + (size_t)row * WDIM;
    float v0 = p[lane], v1 = p[lane + 32];
    double s = (double)v0 * v0 + (double)v1 * v1;
    #pragma unroll
    for (int o = 16; o; o >>= 1) s += __shfl_xor_sync(0xffffffffu, s, o);
    if (lane == 0) g_nrm[row] = fmaxf(__fsqrt_rn((float)s), 1e-12f);
}

// ============================================================
// K1b: normalize codebook rows; also emit bf16 hi/lo split.
// ============================================================
__global__ void k_codebook(const float* __restrict__ emb) {
    int k    = blockIdx.x * 8 + (threadIdx.x >> 5);
    int lane = threadIdx.x & 31;
    const float* e = emb + (size_t)k * CDIM;
    float v[8];
    double s = 0.0;
    #pragma unroll
    for (int i = 0; i < 8; i++) { v[i] = e[lane + i * 32]; s += (double)v[i] * v[i]; }
    #pragma unroll
    for (int o = 16; o; o >>= 1) s += __shfl_xor_sync(0xffffffffu, s, o);
    float n = fmaxf(__fsqrt_rn((float)s), 1e-12f);
    double s2 = 0.0;
    #pragma unroll
    for (int i = 0; i < 8; i++) {
        float t = __fdiv_rn(v[i], n);
        size_t o = (size_t)k * CDIM + lane + i * 32;
        g_wn[o] = t;
        __nv_bfloat16 h = __float2bfloat16(t);
        g_wh[o] = h;
        g_wl[o] = __float2bfloat16(t - __bfloat162float(h));
        s2 += (double)t * t;
    }
    #pragma unroll
    for (int o = 16; o; o >>= 1) s2 += __shfl_xor_sync(0xffffffffu, s2, o);
    if (lane == 0) g_csq[k] = (float)s2;
}

// ============================================================
// K2: fused normalize + transpose [B,C,HW] -> [B*HW,C]; emit bf16 hi/lo too.
// ============================================================
__global__ void k_transpose(const float* __restrict__ z) {
    __shared__ float tile[32][33];
    int b = blockIdx.z, c0 = blockIdx.y * 32, hw0 = blockIdx.x * 32;
    int tx = threadIdx.x, ty = threadIdx.y;
    int h = hw0 >> 6;
    #pragma unroll
    for (int i = 0; i < 4; i++) {
        int c = c0 + ty + i * 8;
        float v = z[((size_t)(b * CDIM + c)) * HW + hw0 + tx];
        v = __fdiv_rn(v, g_nrm[(b * CDIM + c) * HDIM + h]);
        tile[ty + i * 8][tx] = v;
    }
    __syncthreads();
    #pragma unroll
    for (int i = 0; i < 4; i++) {
        int hwl = ty + i * 8;
        size_t o = ((size_t)(b * HW + hw0 + hwl)) * CDIM + c0 + tx;
        float v = tile[tx][hwl];
        g_zf[o] = v;
        __nv_bfloat16 hh = __float2bfloat16(v);
        g_zh[o] = hh;
        g_zl[o] = __float2bfloat16(v - __bfloat162float(hh));
    }
}

// ============================================================
// K3: tensor-core GEMM + argmin, split-bf16 (zh*wh + zh*wl + zl*wh).
// Block: 128 rows x all 1024 codes. 8 warps, warp = m16 x n64 chunk.
// A (hi+lo) resident in smem; B streamed in 64-code chunks.
// score = csq - 2*(main + corr). Margin < TAU -> flagged for rescue.
// ============================================================
__global__ __launch_bounds__(256) void k_argmin_mma(float* __restrict__ outIdxF) {
    extern __shared__ __align__(16) char smem[];
    __nv_bfloat16* sAh = (__nv_bfloat16*)smem;              // [128][APAD]
    __nv_bfloat16* sAl = sAh + 128 * APAD;
    __nv_bfloat16* sBh = sAl + 128 * APAD;                  // [64][APAD]
    __nv_bfloat16* sBl = sBh + 64 * APAD;
    float*        scsq = (float*)(sBl + 64 * APAD);         // [1024]

    int tid = threadIdx.x, wid = tid >> 5, lane = tid & 31;
    size_t rowBase = (size_t)blockIdx.x * 128;

    // stage A (128 rows x 256 bf16, hi+lo) and csq
    for (int idx = tid; idx < 128 * 32; idx += 256) {
        int r = idx >> 5, q = (idx & 31) << 3;
        *(uint4*)(sAh + r * APAD + q) = *(const uint4*)(g_zh + (rowBase + r) * CDIM + q);
        *(uint4*)(sAl + r * APAD + q) = *(const uint4*)(g_zl + (rowBase + r) * CDIM + q);
    }
    for (int i = tid; i < KCODES; i += 256) scsq[i] = g_csq[i];

    // ldmatrix lane addressing (canonical m16n8k16 fragment layouts)
    // A x4: lanes 0-15 -> rows 0..15 @k0 ; lanes 16-31 -> rows 0..15 @k+8
    int aRow  = wid * 16 + (lane & 15);
    int aKofs = (lane >> 4) << 3;
    uint32_t aH = smem_u32(sAh + aRow * APAD + aKofs);
    uint32_t aL = smem_u32(sAl + aRow * APAD + aKofs);
    // B x4 (tiles 2p,2p+1): lanes 0-7 code+0..7 @k0; 8-15 same @k+8;
    //                       16-23 code+8..15 @k0; 24-31 @k+8
    int bCode = ((lane >> 4) << 3) + (lane & 7);
    int bKofs = ((lane >> 3) & 1) << 3;
    uint32_t bH = smem_u32(sBh + bCode * APAD + bKofs);
    uint32_t bL = smem_u32(sBl + bCode * APAD + bKofs);

    float bests[2]  = {3.0e38f, 3.0e38f};
    float bests2[2] = {3.0e38f, 3.0e38f};
    int   bestk[2]  = {0, 0};

    for (int cb = 0; cb < 16; cb++) {
        __syncthreads();
        for (int idx = tid; idx < 64 * 32; idx += 256) {
            int r = idx >> 5, q = (idx & 31) << 3;
            *(uint4*)(sBh + r * APAD + q) = *(const uint4*)(g_wh + (size_t)(cb * 64 + r) * CDIM + q);
            *(uint4*)(sBl + r * APAD + q) = *(const uint4*)(g_wl + (size_t)(cb * 64 + r) * CDIM + q);
        }
        __syncthreads();

        float mainA[8][4], corr[8][4];
        #pragma unroll
        for (int t = 0; t < 8; t++)
            #pragma unroll
            for (int e = 0; e < 4; e++) { mainA[t][e] = 0.f; corr[t][e] = 0.f; }

        #pragma unroll 4
        for (int ks = 0; ks < 16; ks++) {
            uint32_t ah[4], al[4];
            ldsm4(ah, aH + ks * 32);          // 16 bf16 = 32B per k-step
            ldsm4(al, aL + ks * 32);
            #pragma unroll
            for (int p = 0; p < 4; p++) {
                uint32_t bh[4], bl[4];
                uint32_t off = (uint32_t)(p * 16 * APAD + ks * 16) * 2;
                ldsm4(bh, bH + off);
                ldsm4(bl, bL + off);
                mma_bf16(mainA[2 * p],     ah, &bh[0]);
                mma_bf16(corr [2 * p],     ah, &bl[0]);
                mma_bf16(corr [2 * p],     al, &bh[0]);
                mma_bf16(mainA[2 * p + 1], ah, &bh[2]);
                mma_bf16(corr [2 * p + 1], ah, &bl[2]);
                mma_bf16(corr [2 * p + 1], al, &bh[2]);
            }
        }

        // fold chunk into running (best, second); per-slot code order ascending
        #pragma unroll
        for (int t = 0; t < 8; t++) {
            #pragma unroll
            for (int e = 0; e < 4; e++) {
                int code = cb * 64 + t * 8 + ((lane & 3) << 1) + (e & 1);
                float sc = fmaf(-2.0f, mainA[t][e] + corr[t][e], scsq[code]);
                int s = e >> 1;
                if (sc < bests[s]) {
                    bests2[s] = bests[s]; bests[s] = sc; bestk[s] = code;
                } else if (sc < bests2[s]) {
                    bests2[s] = sc;
                }
            }
        }
    }

    // reduce across the 4-lane column group (same row), k tie-break
    #pragma unroll
    for (int s = 0; s < 2; s++) {
        float w1 = bests[s], w2 = bests2[s];
        int   k1 = bestk[s];
        #pragma unroll
        for (int off = 1; off < 4; off <<= 1) {
            float o1 = __shfl_xor_sync(0xffffffffu, w1, off);
            float o2 = __shfl_xor_sync(0xffffffffu, w2, off);
            int   ok = __shfl_xor_sync(0xffffffffu, k1, off);
            if (o1 < w1 || (o1 == w1 && ok < k1)) {
                w2 = fminf(w1, o2); w1 = o1; k1 = ok;
            } else {
                w2 = fminf(w2, o1);
            }
        }
        if ((lane & 3) == 0) {
            size_t n = rowBase + wid * 16 + (lane >> 2) + s * 8;
            g_idx[n]   = k1;
            outIdxF[n] = (float)k1;
            if (w2 - w1 < TAU) {
                int pos = atomicAdd(&g_nflag, 1);
                g_flag[pos] = (int)n;
            }
        }
    }
}

// ============================================================
// K3b: precise re-scoring of near-tie pixels (compensated fp32 Dot2,
// then reference's exact fp32 formula with first-index tie-break).
// ============================================================
__device__ __forceinline__ float dot2_256(const float* __restrict__ a,
                                          const float* __restrict__ b) {
    float s = 0.f, comp = 0.f;
    #pragma unroll 8
    for (int c = 0; c < CDIM; c++) {
        float p  = __fmul_rn(a[c], b[c]);
        float e  = __fmaf_rn(a[c], b[c], -p);
        float t  = __fadd_rn(s, p);
        float bv = __fsub_rn(t, s);
        float e2 = __fadd_rn(__fsub_rn(s, __fsub_rn(t, bv)), __fsub_rn(p, bv));
        comp = __fadd_rn(comp, __fadd_rn(e, e2));
        s = t;
    }
    return __fadd_rn(s, comp);
}

__global__ __launch_bounds__(256) void k_precise(float* __restrict__ outIdxF) {
    __shared__ float szf[CDIM];
    __shared__ float srq;
    __shared__ float rs[256];
    __shared__ int   rk[256];
    int nf = g_nflag;
    for (int it = blockIdx.x; it < nf; it += gridDim.x) {
        int n = g_flag[it];
        szf[threadIdx.x] = g_zf[(size_t)n * CDIM + threadIdx.x];
        __syncthreads();
        if (threadIdx.x == 0) srq = dot2_256(szf, szf);
        __syncthreads();
        float rq = srq;
        float bs = 3.0e38f;
        int   bk = 0x7fffffff;
        #pragma unroll
        for (int j = 0; j < 4; j++) {
            int k = threadIdx.x + j * 256;
            float dot = dot2_256(szf, g_wn + (size_t)k * CDIM);
            float d = __fsub_rn(__fadd_rn(rq, g_csq[k]), __fmul_rn(2.0f, dot));
            if (d < bs || (d == bs && k < bk)) { bs = d; bk = k; }
        }
        rs[threadIdx.x] = bs; rk[threadIdx.x] = bk;
        __syncthreads();
        if (threadIdx.x == 0) {
            float b = rs[0]; int kk = rk[0];
            #pragma unroll 8
            for (int t = 1; t < 256; t++) {
                if (rs[t] < b || (rs[t] == b && rk[t] < kk)) { b = rs[t]; kk = rk[t]; }
            }
            g_idx[n]   = kk;
            outIdxF[n] = (float)kk;
        }
        __syncthreads();
    }
}

// ============================================================
// K4: gather + straight-through + transpose back + loss partials.
// ============================================================
__global__ void k_gather(float* __restrict__ out, const float* __restrict__ emb) {
    __shared__ float tile[32][33];
    __shared__ float red[8];
    int b = blockIdx.z, c0 = blockIdx.y * 32, hw0 = blockIdx.x * 32;
    int tx = threadIdx.x, ty = threadIdx.y;
    float lsum = 0.f;
    #pragma unroll
    for (int i = 0; i < 4; i++) {
        int hwl = ty + i * 8;
        size_t n = (size_t)b * HW + hw0 + hwl;
        float zp = g_zf[n * CDIM + c0 + tx];
        int   k  = g_idx[n];
        float e  = emb[(size_t)k * CDIM + c0 + tx];
        float d  = __fsub_rn(e, zp);
        tile[hwl][tx] = __fadd_rn(zp, d);
        lsum = __fmaf_rn(d, d, lsum);
    }
    __syncthreads();
    #pragma unroll
    for (int i = 0; i < 4; i++) {
        int cl = ty + i * 8;
        out[((size_t)(b * CDIM + c0 + cl)) * HW + hw0 + tx] = tile[tx][cl];
    }
    #pragma unroll
    for (int o = 16; o; o >>= 1) lsum += __shfl_xor_sync(0xffffffffu, lsum, o);
    int tid = ty * 32 + tx;
    if ((tid & 31) == 0) red[tid >> 5] = lsum;
    __syncthreads();
    if (tid == 0) {
        float s = 0.f;
        #pragma unroll
        for (int w = 0; w < 8; w++) s += red[w];
        g_part[((size_t)blockIdx.z * gridDim.y + blockIdx.y) * gridDim.x + blockIdx.x] = s;
    }
}

// ============================================================
// K5: final loss. loss = 1.25 * sum / ZSIZE
// ============================================================
__global__ void k_loss(float* __restrict__ out) {
    __shared__ float red[8];
    int tid = threadIdx.x;
    float s = 0.f;
    for (int i = tid; i < NPART; i += 256) s += g_part[i];
    #pragma unroll
    for (int o = 16; o; o >>= 1) s += __shfl_xor_sync(0xffffffffu, s, o);
    if ((tid & 31) == 0) red[tid >> 5] = s;
    __syncthreads();
    if (tid == 0) {
        float t = 0.f;
        #pragma unroll
        for (int w = 0; w < 8; w++) t += red[w];
        out[(size_t)ZSIZE + NROWS] = 1.25f * t / (float)ZSIZE;
    }
}

// ============================================================
// launch: out layout = [ z_q (16777216 f32) | idx-as-f32 (65536) | loss (1) ]
// ============================================================
#define SMEM_MMA ((128 * APAD * 2 + 64 * APAD * 2) * 2 + KCODES * 4)

extern "C" void kernel_launch(void* const* d_in, const int* in_sizes, int n_in,
                              void* d_out, int out_size) {
    const float* z   = (const float*)d_in[0];
    const float* emb = (const float*)d_in[1];
    float* out = (float*)d_out;

    cudaFuncSetAttribute(k_argmin_mma, cudaFuncAttributeMaxDynamicSharedMemorySize, SMEM_MMA);

    k_rownorm   <<<BATCH * CDIM * HDIM / 8, 256>>>(z);
    k_codebook  <<<KCODES / 8, 256>>>(emb);
    k_transpose <<<dim3(HW / 32, CDIM / 32, BATCH), dim3(32, 8)>>>(z);
    k_argmin_mma<<<NROWS / 128, 256, SMEM_MMA>>>(out + ZSIZE);
    k_precise   <<<256, 256>>>(out + ZSIZE);
    k_gather    <<<dim3(HW / 32, CDIM / 32, BATCH), dim3(32, 8)>>>(out, emb);
    k_loss      <<<1, 256>>>(out);
}